// round 3
// baseline (speedup 1.0000x reference)
#include <cuda_runtime.h>
#include <math.h>

// ---------------------------------------------------------------------------
// MultiScaleDeformableAttention2D — fp32 baseline
//   B=4, C=256, HEADS=8, LEVELS=4, POINTS=4, HQ=WQ=64, HD=32
//   FEAT_HW = {64,32,16,8}
// Pipeline:
//   1. q = q_w @ query                       (1x1 GEMM)
//   2. off = conv3x3(q, off_w)+off_b         (9-tap shifted GEMM)
//   3. logit = conv3x3(q, attn_w)+attn_b     (9-tap shifted GEMM)
//   4. softmax over 16 per (b,head,px)
//   5. v_l = v_w[l] @ feat_l  -> head-blocked channel-last layout
//   6. deformable sampling (warp per (b,head,px), lane = channel)
//   7. out = out_w @ S + query -> BN -> SiLU  (fused epilogue)
// ---------------------------------------------------------------------------

#define CIN    256
#define NQ     4096      // 64*64
#define BATCH  4
#define HEADS  8
#define HD     32

// ---- scratch (device globals; no allocation allowed) ----------------------
__device__ float g_q[BATCH * 256 * NQ];       // q projection
__device__ float g_off[BATCH * 256 * NQ];     // raw offset conv output
__device__ float g_logit[BATCH * 128 * NQ];   // logits -> softmaxed in place
__device__ float g_v[5570560];                // projected values, all levels
__device__ float g_S[BATCH * 256 * NQ];       // sampled attention output (NCHW)
__device__ float g_wpack[1277952];            // packed weights (K-major)
__device__ float g_bnsc[256];
__device__ float g_bnsh[256];

// packed-weight offsets inside g_wpack
#define WP_Q    0
#define WP_OFF  65536        // 256*256*1
#define WP_ATTN 655360       // + 256*256*9
#define WP_V    950272       // + 128*256*9
#define WP_OUT  1212416      // + 4*256*256

// v-level offsets inside g_v (elements)
__device__ __constant__ int c_voff[4] = {0, 4194304, 5242880, 5505024};
__device__ __constant__ int c_hw[4]   = {64, 32, 16, 8};

// ---------------------------------------------------------------------------
// Weight repack: src (M, C, TAPS) row-major -> dst[(tap*C + c)*M + o]
// ---------------------------------------------------------------------------
__global__ void pack_weights(const float* __restrict__ src, float* __restrict__ dst,
                             int M, int taps) {
    int idx = blockIdx.x * blockDim.x + threadIdx.x;
    int total = M * CIN * taps;
    if (idx >= total) return;
    int o = idx / (CIN * taps);
    int r = idx - o * (CIN * taps);
    int c = r / taps;
    int t = r - c * taps;
    dst[(t * CIN + c) * M + o] = src[idx];
}

__global__ void bn_prep(const float* __restrict__ g, const float* __restrict__ be,
                        const float* __restrict__ mu, const float* __restrict__ var) {
    int o = threadIdx.x;
    float sc = g[o] * rsqrtf(var[o] + 1e-5f);
    g_bnsc[o] = sc;
    g_bnsh[o] = be[o] - mu[o] * sc;
}

// ---------------------------------------------------------------------------
// Tiled GEMM / shifted-conv kernel.
//   Y[b][oc][px] = sum_{tap,c} Wp[(tap*C+c)*M+oc] * X[b][c][shift(px,tap)] (+bias)
// Tile: 64 oc x 256 px, BK=8, 256 threads, 8x8 register tile per thread.
// MODE 0: standard NCHW write (+bias)
// MODE 1: v-proj write -> ((b*8 + oc/32)*N + px)*32 + oc%32   (head-blocked, ch-last)
// MODE 2: out-proj epilogue: + resid, BN(scale/shift), SiLU -> NCHW
// ---------------------------------------------------------------------------
template <int TAPS, int MODE>
__global__ void __launch_bounds__(256) gemm_conv(
    const float* __restrict__ X, const float* __restrict__ Wp,
    const float* __restrict__ bias, float* __restrict__ Y,
    int M, int H, int Wd,
    const float* __restrict__ resid) {
    const int N   = H * Wd;
    const int b   = blockIdx.z;
    const int oc0 = blockIdx.y * 64;
    const int n0  = blockIdx.x * 256;
    const float* Xb = X + (size_t)b * CIN * N;

    __shared__ float Ws[8][64];
    __shared__ float Xs[8][256];

    float acc[8][8];
#pragma unroll
    for (int i = 0; i < 8; i++)
#pragma unroll
        for (int j = 0; j < 8; j++) acc[i][j] = 0.f;

    const int tid = threadIdx.x;
    const int tm  = tid >> 5;    // 0..7  (oc groups)
    const int tn  = tid & 31;    // 0..31 (px groups)
    const int px  = n0 + tid;    // pixel this thread stages into Xs

#pragma unroll 1
    for (int tap = 0; tap < TAPS; ++tap) {
        int sidx; bool valid;
        if (TAPS == 9) {
            // conv only runs on the 64x64 query grid
            int y  = px >> 6, x = px & 63;
            int ys = y + tap / 3 - 1;
            int xs = x + tap % 3 - 1;
            valid = (ys >= 0 && ys < 64 && xs >= 0 && xs < 64);
            sidx  = ys * 64 + xs;
        } else {
            valid = (px < N);
            sidx  = px;
        }
#pragma unroll 1
        for (int c0 = 0; c0 < CIN; c0 += 8) {
#pragma unroll
            for (int i = 0; i < 2; i++) {
                int lin = tid + i * 256;
                Ws[lin >> 6][lin & 63] =
                    Wp[(size_t)(tap * CIN + c0 + (lin >> 6)) * M + oc0 + (lin & 63)];
            }
#pragma unroll
            for (int i = 0; i < 8; i++)
                Xs[i][tid] = valid ? Xb[(size_t)(c0 + i) * N + sidx] : 0.f;
            __syncthreads();
#pragma unroll
            for (int k = 0; k < 8; k++) {
                float a[8], bb[8];
#pragma unroll
                for (int i = 0; i < 8; i++) a[i] = Ws[k][tm * 8 + i];
#pragma unroll
                for (int j = 0; j < 8; j++) bb[j] = Xs[k][tn * 8 + j];
#pragma unroll
                for (int i = 0; i < 8; i++)
#pragma unroll
                    for (int j = 0; j < 8; j++) acc[i][j] += a[i] * bb[j];
            }
            __syncthreads();
        }
    }

    // epilogue
#pragma unroll
    for (int i = 0; i < 8; i++) {
        int oc = oc0 + tm * 8 + i;
        float bi = (MODE == 0 && bias != nullptr) ? bias[oc] : 0.f;
#pragma unroll
        for (int j = 0; j < 8; j++) {
            int p = n0 + tn * 8 + j;
            if (p >= N) continue;
            float t = acc[i][j] + bi;
            if (MODE == 0) {
                Y[((size_t)b * M + oc) * N + p] = t;
            } else if (MODE == 1) {
                Y[((size_t)(b * HEADS + (oc >> 5)) * N + p) * HD + (oc & 31)] = t;
            } else {
                t += resid[((size_t)b * CIN + oc) * N + p];
                float xn = t * g_bnsc[oc] + g_bnsh[oc];
                Y[((size_t)b * CIN + oc) * N + p] = xn / (1.f + __expf(-xn));
            }
        }
    }
}

// ---------------------------------------------------------------------------
// Softmax over 16 (level,point) logits per (b, head, px). In place.
// ---------------------------------------------------------------------------
__global__ void softmax16() {
    int idx = blockIdx.x * blockDim.x + threadIdx.x;
    if (idx >= BATCH * HEADS * NQ) return;
    int px   = idx & (NQ - 1);
    int head = (idx >> 12) & 7;
    int b    = idx >> 15;
    float* base = g_logit + ((size_t)b * 128 + head * 16) * NQ + px;
    float v[16];
    float m = -1e30f;
#pragma unroll
    for (int j = 0; j < 16; j++) { v[j] = base[j * NQ]; m = fmaxf(m, v[j]); }
    float s = 0.f;
#pragma unroll
    for (int j = 0; j < 16; j++) { v[j] = __expf(v[j] - m); s += v[j]; }
    float inv = 1.f / s;
#pragma unroll
    for (int j = 0; j < 16; j++) base[j * NQ] = v[j] * inv;
}

// ---------------------------------------------------------------------------
// Deformable sampling. One warp per (b, head, px); lane = channel d (HD=32).
// v layout per level: (b*8+head, y, x, d) -> 128B coalesced corner reads.
// Writes S in NCHW: S[b][head*32+d][px].
// ---------------------------------------------------------------------------
__global__ void __launch_bounds__(256) sample_kernel() {
    int gtid = blockIdx.x * blockDim.x + threadIdx.x;
    int wg   = gtid >> 5;              // warp id: 0 .. B*HEADS*NQ-1
    int lane = gtid & 31;
    int px   = wg & (NQ - 1);
    int head = (wg >> 12) & 7;
    int b    = wg >> 15;
    int py  = px >> 6;
    int pxx = px & 63;
    float refx = -1.f + (2.f / 63.f) * (float)pxx;
    float refy = -1.f + (2.f / 63.f) * (float)py;

    const float* offp = g_off + (size_t)b * 256 * NQ + px;
    const float* attp = g_logit + ((size_t)b * 128 + head * 16) * NQ + px;

    float acc = 0.f;
#pragma unroll
    for (int lvl = 0; lvl < 4; lvl++) {
        int Wl = c_hw[lvl];
        const float* vb = g_v + c_voff[lvl] + (size_t)(b * HEADS + head) * Wl * Wl * HD;
        float sc = 0.5f * (float)(Wl - 1);
#pragma unroll
        for (int pt = 0; pt < 4; pt++) {
            int j  = lvl * 4 + pt;
            int ch = ((head * 4 + lvl) * 4 + pt) * 2;
            float ox = tanhf(offp[ch * NQ]) * 0.25f;
            float oy = tanhf(offp[(ch + 1) * NQ]) * 0.25f;
            float aw = attp[j * NQ];
            float x = (refx + ox + 1.f) * sc;
            float y = (refy + oy + 1.f) * sc;
            float x0f = floorf(x), y0f = floorf(y);
            float fx = x - x0f, fy = y - y0f;
            int x0 = (int)x0f, y0 = (int)y0f;
            float s = 0.f;
#pragma unroll
            for (int cy = 0; cy < 2; cy++) {
                int yi = y0 + cy;
                if (yi < 0 || yi >= Wl) continue;
                float wy = cy ? fy : (1.f - fy);
#pragma unroll
                for (int cx = 0; cx < 2; cx++) {
                    int xi = x0 + cx;
                    if (xi < 0 || xi >= Wl) continue;
                    float wx = cx ? fx : (1.f - fx);
                    s += wy * wx * vb[(yi * Wl + xi) * HD + lane];
                }
            }
            acc += aw * s;
        }
    }
    g_S[((size_t)b * 256 + head * HD + lane) * NQ + px] = acc;
}

// ---------------------------------------------------------------------------
// Host launcher
// ---------------------------------------------------------------------------
extern "C" void kernel_launch(void* const* d_in, const int* in_sizes, int n_in,
                              void* d_out, int out_size) {
    const float* query  = (const float*)d_in[0];
    const float* feats[4] = {(const float*)d_in[1], (const float*)d_in[2],
                             (const float*)d_in[3], (const float*)d_in[4]};
    const float* q_w    = (const float*)d_in[5];
    const float* v_w    = (const float*)d_in[6];
    const float* out_w  = (const float*)d_in[7];
    const float* off_w  = (const float*)d_in[8];
    const float* off_b  = (const float*)d_in[9];
    const float* attn_w = (const float*)d_in[10];
    const float* attn_b = (const float*)d_in[11];
    const float* bng    = (const float*)d_in[12];
    const float* bnb    = (const float*)d_in[13];
    const float* bnm    = (const float*)d_in[14];
    const float* bnv    = (const float*)d_in[15];

    float *pq, *poff, *plogit, *pv, *pS, *pwp;
    cudaGetSymbolAddress((void**)&pq, g_q);
    cudaGetSymbolAddress((void**)&poff, g_off);
    cudaGetSymbolAddress((void**)&plogit, g_logit);
    cudaGetSymbolAddress((void**)&pv, g_v);
    cudaGetSymbolAddress((void**)&pS, g_S);
    cudaGetSymbolAddress((void**)&pwp, g_wpack);

    // ---- pack weights (K-major) + BN prep ----
    {
        int tot;
        tot = 256 * 256 * 1; pack_weights<<<(tot + 255) / 256, 256>>>(q_w,   pwp + WP_Q,   256, 1);
        tot = 256 * 256 * 9; pack_weights<<<(tot + 255) / 256, 256>>>(off_w, pwp + WP_OFF, 256, 9);
        tot = 128 * 256 * 9; pack_weights<<<(tot + 255) / 256, 256>>>(attn_w,pwp + WP_ATTN,128, 9);
        for (int l = 0; l < 4; l++) {
            tot = 256 * 256 * 1;
            pack_weights<<<(tot + 255) / 256, 256>>>(v_w + l * 65536, pwp + WP_V + l * 65536, 256, 1);
        }
        tot = 256 * 256 * 1; pack_weights<<<(tot + 255) / 256, 256>>>(out_w, pwp + WP_OUT, 256, 1);
        bn_prep<<<1, 256>>>(bng, bnb, bnm, bnv);
    }

    // ---- 1. q projection ----
    gemm_conv<1, 0><<<dim3(16, 4, 4), 256>>>(query, pwp + WP_Q, nullptr, pq, 256, 64, 64, nullptr);

    // ---- 2/3. offset + logit convs ----
    gemm_conv<9, 0><<<dim3(16, 4, 4), 256>>>(pq, pwp + WP_OFF, off_b,  poff,   256, 64, 64, nullptr);
    gemm_conv<9, 0><<<dim3(16, 2, 4), 256>>>(pq, pwp + WP_ATTN, attn_b, plogit, 128, 64, 64, nullptr);

    // ---- 4. softmax ----
    softmax16<<<(BATCH * HEADS * NQ + 255) / 256, 256>>>();

    // ---- 5. value projections per level ----
    {
        const int hw[4]   = {64, 32, 16, 8};
        const int voff[4] = {0, 4194304, 5242880, 5505024};
        for (int l = 0; l < 4; l++) {
            int n = hw[l] * hw[l];
            dim3 grid((n + 255) / 256, 4, 4);
            gemm_conv<1, 1><<<grid, 256>>>(feats[l], pwp + WP_V + l * 65536, nullptr,
                                           pv + voff[l], 256, hw[l], hw[l], nullptr);
        }
    }

    // ---- 6. deformable sampling ----
    sample_kernel<<<(BATCH * HEADS * NQ * 32) / 256, 256>>>();

    // ---- 7. output projection + residual + BN + SiLU ----
    gemm_conv<1, 2><<<dim3(16, 4, 4), 256>>>(pS, pwp + WP_OUT, nullptr, (float*)d_out,
                                             256, 64, 64, query);
}

// round 5
// speedup vs baseline: 1.5398x; 1.5398x over previous
#include <cuda_runtime.h>
#include <cuda_bf16.h>
#include <math.h>
#include <stdint.h>

// ---------------------------------------------------------------------------
// MultiScaleDeformableAttention2D — HMMA (mma.sync) bf16-split conv core
//   (tcgen05 unavailable: harness targets plain sm_103, no 'a' features)
//   B=4, C=256, HEADS=8, LEVELS=4, POINTS=4, HQ=WQ=64, HD=32
// ---------------------------------------------------------------------------

#define CIN    256
#define NQ     4096
#define BATCH  4
#define HEADS  8
#define HD     32

// ---- scratch (device globals) ---------------------------------------------
__device__ float g_q[BATCH * 256 * NQ];
__device__ float g_off[BATCH * 256 * NQ];
__device__ float g_logit[BATCH * 128 * NQ];
__device__ float g_v[5570560];
__device__ float g_S[BATCH * 256 * NQ];
__device__ float g_wpack[1277952];            // fp32 packed weights (q/v/out)
__device__ float g_bnsc[256];
__device__ float g_bnsh[256];

// bf16 split data for HMMA conv
__device__ __nv_bfloat16 g_qh[BATCH * NQ * 256];   // channel-last hi
__device__ __nv_bfloat16 g_ql[BATCH * NQ * 256];   // channel-last lo
__device__ __nv_bfloat16 g_wh[884736];             // conv weights hi (off then attn)
__device__ __nv_bfloat16 g_wl[884736];             // conv weights lo
#define WB_ATTN 589824   // 256*2304

#define WP_Q    0
#define WP_V    950272
#define WP_OUT  1212416

__device__ __constant__ int c_voff[4] = {0, 4194304, 5242880, 5505024};
__device__ __constant__ int c_hw[4]   = {64, 32, 16, 8};

// ===========================================================================
// PTX helpers (sm_80-era features only — valid on plain sm_103 target)
// ===========================================================================
__device__ __forceinline__ uint32_t smem_u32(const void* p) {
    uint32_t a;
    asm("{ .reg .u64 t; cvta.to.shared.u64 t, %1; cvt.u32.u64 %0, t; }" : "=r"(a) : "l"(p));
    return a;
}
__device__ __forceinline__ void cp16(uint32_t dst, const void* src, uint32_t sz) {
    asm volatile("cp.async.cg.shared.global [%0], [%1], 16, %2;"
                 :: "r"(dst), "l"(__cvta_generic_to_global(src)), "r"(sz) : "memory");
}
#define CP_COMMIT() asm volatile("cp.async.commit_group;" ::: "memory")
__device__ __forceinline__ void ldmat_x4(uint32_t* r, uint32_t addr) {
    asm volatile("ldmatrix.sync.aligned.m8n8.x4.shared.b16 {%0,%1,%2,%3}, [%4];"
                 : "=r"(r[0]), "=r"(r[1]), "=r"(r[2]), "=r"(r[3]) : "r"(addr));
}
__device__ __forceinline__ void mma16816(float* d, const uint32_t* a, const uint32_t* b) {
    asm volatile("mma.sync.aligned.m16n8k16.row.col.f32.bf16.bf16.f32 "
        "{%0,%1,%2,%3}, {%4,%5,%6,%7}, {%8,%9}, {%0,%1,%2,%3};"
        : "+f"(d[0]), "+f"(d[1]), "+f"(d[2]), "+f"(d[3])
        : "r"(a[0]), "r"(a[1]), "r"(a[2]), "r"(a[3]), "r"(b[0]), "r"(b[1]));
}

// ===========================================================================
// Prep kernels
// ===========================================================================
__global__ void pack_weights(const float* __restrict__ src, float* __restrict__ dst,
                             int M, int taps) {
    int idx = blockIdx.x * blockDim.x + threadIdx.x;
    int total = M * CIN * taps;
    if (idx >= total) return;
    int o = idx / (CIN * taps);
    int r = idx - o * (CIN * taps);
    int c = r / taps;
    int t = r - c * taps;
    dst[(t * CIN + c) * M + o] = src[idx];
}

// conv weights (M, 256, 3, 3) -> hi/lo bf16, layout [(tap*4+chunk)*M + oc][64]
__global__ void pack_conv_bf16(const float* __restrict__ src,
                               __nv_bfloat16* __restrict__ dh,
                               __nv_bfloat16* __restrict__ dl, int M) {
    int idx = blockIdx.x * blockDim.x + threadIdx.x;
    int total = M * 2304;
    if (idx >= total) return;
    int o = idx / 2304;
    int r = idx - o * 2304;
    int c = r / 9;
    int t = r - c * 9;
    float v = src[idx];
    __nv_bfloat16 hi = __float2bfloat16(v);
    float lo = v - __bfloat162float(hi);
    int di = (((t * 4 + (c >> 6)) * M + o) << 6) + (c & 63);
    dh[di] = hi;
    dl[di] = __float2bfloat16(lo);
}

__global__ void bn_prep(const float* __restrict__ g, const float* __restrict__ be,
                        const float* __restrict__ mu, const float* __restrict__ var) {
    int o = threadIdx.x;
    float sc = g[o] * rsqrtf(var[o] + 1e-5f);
    g_bnsc[o] = sc;
    g_bnsh[o] = be[o] - mu[o] * sc;
}

// q (NCHW fp32) -> channel-last bf16 hi/lo. grid (128, 4), 256 thr.
__global__ void __launch_bounds__(256) q_split() {
    __shared__ float t[256][33];
    int b = blockIdx.y, p0 = blockIdx.x * 32;
    int tid = threadIdx.x, w = tid >> 5, lane = tid & 31;
#pragma unroll
    for (int rr = 0; rr < 32; rr++) {
        int c = rr * 8 + w;
        t[c][lane] = g_q[((size_t)(b * 256 + c)) * NQ + p0 + lane];
    }
    __syncthreads();
#pragma unroll
    for (int rr = 0; rr < 4; rr++) {
        int px = rr * 8 + w;
        int c0 = lane * 8;
        alignas(16) __nv_bfloat16 h[8], l[8];
#pragma unroll
        for (int k = 0; k < 8; k++) {
            float v = t[c0 + k][px];
            h[k] = __float2bfloat16(v);
            l[k] = __float2bfloat16(v - __bfloat162float(h[k]));
        }
        size_t dst = ((size_t)(b * NQ + p0 + px) << 8) + c0;
        *(uint4*)&g_qh[dst] = *(const uint4*)h;
        *(uint4*)&g_ql[dst] = *(const uint4*)l;
    }
}

// ===========================================================================
// HMMA conv kernel: Y[b][oc][px] = conv3x3(q)[oc][px] + bias[oc]
// CTA tile: 128 px (M) x 128 oc (N). K = 9 taps * 256 c = 36 chunks of 64.
// 3-split bf16: AhBh + AhBl + AlBh, fp32 register accumulators.
// 8 warps in 4x2; warp tile 32m x 64n.
// SMEM per buffer: AH/AL/BH/BL, each 128 rows x 144B (64 bf16 padded).
// Double-buffered via cp.async.
// ===========================================================================
#define TILE_B   18432            // 128 * 144
#define BUF_B    73728            // 4 tiles
#define SM_CONV  147456           // 2 buffers

template <int MOUT>
__global__ void __launch_bounds__(256) conv_hmma(
    const __nv_bfloat16* __restrict__ Ah, const __nv_bfloat16* __restrict__ Al,
    const __nv_bfloat16* __restrict__ Bh, const __nv_bfloat16* __restrict__ Bl,
    const float* __restrict__ bias, float* __restrict__ Y) {
    extern __shared__ char sm[];
    const uint32_t smb = smem_u32(sm);
    const int tid  = threadIdx.x;
    const int wid  = tid >> 5, lane = tid & 31;
    const int wm   = wid >> 1, wn = wid & 1;
    const int p0   = blockIdx.x * 128;
    const int oc0  = blockIdx.y * 128;
    const int bz   = blockIdx.z;

    float acc[2][8][4];
#pragma unroll
    for (int i = 0; i < 2; i++)
#pragma unroll
        for (int j = 0; j < 8; j++)
#pragma unroll
            for (int k = 0; k < 4; k++) acc[i][j][k] = 0.f;

    // ---- staging helper (cp.async, 16 per thread per chunk) ----
    auto stage = [&](int it, int bufoff) {
        int tap = it >> 2, ch = it & 3;
        int dy = tap / 3 - 1, dx = tap % 3 - 1;
#pragma unroll
        for (int s = tid; s < 1024; s += 256) {
            int r = s >> 3, seg = s & 7;
            int px = p0 + r;
            int ys = (px >> 6) + dy, xs = (px & 63) + dx;
            uint32_t valid = (((unsigned)ys < 64u) && ((unsigned)xs < 64u)) ? 16u : 0u;
            size_t asrc = valid ? (((size_t)(bz * NQ + ys * 64 + xs) << 8) + ch * 64 + seg * 8)
                                : (size_t)0;
            uint32_t ad = smb + bufoff + r * 144 + seg * 16;
            cp16(ad,             Ah + asrc, valid);
            cp16(ad + TILE_B,    Al + asrc, valid);
            size_t bsrc = ((size_t)(it * MOUT + oc0 + r) << 6) + seg * 8;
            cp16(ad + 2 * TILE_B, Bh + bsrc, 16u);
            cp16(ad + 3 * TILE_B, Bl + bsrc, 16u);
        }
        CP_COMMIT();
    };

    stage(0, 0);

#pragma unroll 1
    for (int it = 0; it < 36; ++it) {
        const int bufoff = (it & 1) * BUF_B;
        if (it < 35) {
            stage(it + 1, ((it + 1) & 1) * BUF_B);
            asm volatile("cp.async.wait_group 1;" ::: "memory");
        } else {
            asm volatile("cp.async.wait_group 0;" ::: "memory");
        }
        __syncthreads();

        // ---- compute this chunk: 4 k16 steps ----
#pragma unroll
        for (int ks = 0; ks < 4; ks++) {
            const int k0 = ks * 16;
            uint32_t ah[2][4], al[2][4];
#pragma unroll
            for (int i = 0; i < 2; i++) {
                uint32_t ad = smb + bufoff + (wm * 32 + i * 16 + (lane & 15)) * 144
                            + k0 * 2 + ((lane >> 4) << 4);
                ldmat_x4(ah[i], ad);
                ldmat_x4(al[i], ad + TILE_B);
            }
#pragma unroll
            for (int j = 0; j < 4; j++) {
                uint32_t brow = wn * 64 + j * 16 + ((lane >> 4) << 3) + (lane & 7);
                uint32_t bd = smb + bufoff + 2 * TILE_B + brow * 144
                            + k0 * 2 + (((lane >> 3) & 1) << 4);
                uint32_t bh4[4], bl4[4];
                ldmat_x4(bh4, bd);
                ldmat_x4(bl4, bd + TILE_B);
#pragma unroll
                for (int i = 0; i < 2; i++) {
                    mma16816(acc[i][2 * j],     ah[i], bh4);
                    mma16816(acc[i][2 * j + 1], ah[i], bh4 + 2);
                    mma16816(acc[i][2 * j],     ah[i], bl4);
                    mma16816(acc[i][2 * j + 1], ah[i], bl4 + 2);
                    mma16816(acc[i][2 * j],     al[i], bh4);
                    mma16816(acc[i][2 * j + 1], al[i], bh4 + 2);
                }
            }
        }
        __syncthreads();
    }

    // ---- epilogue: d0:(g,2t) d1:(g,2t+1) d2:(g+8,2t) d3:(g+8,2t+1) ----
    const int g = lane >> 2, t = lane & 3;
#pragma unroll
    for (int i = 0; i < 2; i++) {
        int px  = p0 + wm * 32 + i * 16 + g;
#pragma unroll
        for (int j = 0; j < 8; j++) {
            int oc = oc0 + wn * 64 + j * 8 + 2 * t;
            float b0v = bias[oc], b1v = bias[oc + 1];
            size_t r0 = ((size_t)bz * MOUT + oc) * NQ;
            size_t r1 = ((size_t)bz * MOUT + oc + 1) * NQ;
            Y[r0 + px]     = acc[i][j][0] + b0v;
            Y[r1 + px]     = acc[i][j][1] + b1v;
            Y[r0 + px + 8] = acc[i][j][2] + b0v;
            Y[r1 + px + 8] = acc[i][j][3] + b1v;
        }
    }
}

// ===========================================================================
// fp32 tiled GEMM (q/v/out projections)
// ===========================================================================
template <int TAPS, int MODE>
__global__ void __launch_bounds__(256) gemm_conv(
    const float* __restrict__ X, const float* __restrict__ Wp,
    const float* __restrict__ bias, float* __restrict__ Y,
    int M, int H, int Wd,
    const float* __restrict__ resid) {
    const int N   = H * Wd;
    const int b   = blockIdx.z;
    const int oc0 = blockIdx.y * 64;
    const int n0  = blockIdx.x * 256;
    const float* Xb = X + (size_t)b * CIN * N;

    __shared__ float Ws[8][64];
    __shared__ float Xs[8][256];

    float acc[8][8];
#pragma unroll
    for (int i = 0; i < 8; i++)
#pragma unroll
        for (int j = 0; j < 8; j++) acc[i][j] = 0.f;

    const int tid = threadIdx.x;
    const int tm  = tid >> 5;
    const int tn  = tid & 31;
    const int px  = n0 + tid;

#pragma unroll 1
    for (int tap = 0; tap < TAPS; ++tap) {
        int sidx; bool valid;
        if (TAPS == 9) {
            int y  = px >> 6, x = px & 63;
            int ys = y + tap / 3 - 1;
            int xs = x + tap % 3 - 1;
            valid = (ys >= 0 && ys < 64 && xs >= 0 && xs < 64);
            sidx  = ys * 64 + xs;
        } else {
            valid = (px < N);
            sidx  = px;
        }
#pragma unroll 1
        for (int c0 = 0; c0 < CIN; c0 += 8) {
#pragma unroll
            for (int i = 0; i < 2; i++) {
                int lin = tid + i * 256;
                Ws[lin >> 6][lin & 63] =
                    Wp[(size_t)(tap * CIN + c0 + (lin >> 6)) * M + oc0 + (lin & 63)];
            }
#pragma unroll
            for (int i = 0; i < 8; i++)
                Xs[i][tid] = valid ? Xb[(size_t)(c0 + i) * N + sidx] : 0.f;
            __syncthreads();
#pragma unroll
            for (int k = 0; k < 8; k++) {
                float a[8], bb[8];
#pragma unroll
                for (int i = 0; i < 8; i++) a[i] = Ws[k][tm * 8 + i];
#pragma unroll
                for (int j = 0; j < 8; j++) bb[j] = Xs[k][tn * 8 + j];
#pragma unroll
                for (int i = 0; i < 8; i++)
#pragma unroll
                    for (int j = 0; j < 8; j++) acc[i][j] += a[i] * bb[j];
            }
            __syncthreads();
        }
    }

#pragma unroll
    for (int i = 0; i < 8; i++) {
        int oc = oc0 + tm * 8 + i;
        float bi = (MODE == 0 && bias != nullptr) ? bias[oc] : 0.f;
#pragma unroll
        for (int j = 0; j < 8; j++) {
            int p = n0 + tn * 8 + j;
            if (p >= N) continue;
            float t = acc[i][j] + bi;
            if (MODE == 0) {
                Y[((size_t)b * M + oc) * N + p] = t;
            } else if (MODE == 1) {
                Y[((size_t)(b * HEADS + (oc >> 5)) * N + p) * HD + (oc & 31)] = t;
            } else {
                t += resid[((size_t)b * CIN + oc) * N + p];
                float xn = t * g_bnsc[oc] + g_bnsh[oc];
                Y[((size_t)b * CIN + oc) * N + p] = xn / (1.f + __expf(-xn));
            }
        }
    }
}

// ===========================================================================
// Softmax over 16 (level,point) logits per (b, head, px). In place.
// ===========================================================================
__global__ void softmax16() {
    int idx = blockIdx.x * blockDim.x + threadIdx.x;
    if (idx >= BATCH * HEADS * NQ) return;
    int px   = idx & (NQ - 1);
    int head = (idx >> 12) & 7;
    int b    = idx >> 15;
    float* base = g_logit + ((size_t)b * 128 + head * 16) * NQ + px;
    float v[16];
    float m = -1e30f;
#pragma unroll
    for (int j = 0; j < 16; j++) { v[j] = base[j * NQ]; m = fmaxf(m, v[j]); }
    float s = 0.f;
#pragma unroll
    for (int j = 0; j < 16; j++) { v[j] = __expf(v[j] - m); s += v[j]; }
    float inv = 1.f / s;
#pragma unroll
    for (int j = 0; j < 16; j++) base[j * NQ] = v[j] * inv;
}

// ===========================================================================
// Deformable sampling
// ===========================================================================
__global__ void __launch_bounds__(256) sample_kernel() {
    int gtid = blockIdx.x * blockDim.x + threadIdx.x;
    int wg   = gtid >> 5;
    int lane = gtid & 31;
    int px   = wg & (NQ - 1);
    int head = (wg >> 12) & 7;
    int b    = wg >> 15;
    int py  = px >> 6;
    int pxx = px & 63;
    float refx = -1.f + (2.f / 63.f) * (float)pxx;
    float refy = -1.f + (2.f / 63.f) * (float)py;

    const float* offp = g_off + (size_t)b * 256 * NQ + px;
    const float* attp = g_logit + ((size_t)b * 128 + head * 16) * NQ + px;

    float acc = 0.f;
#pragma unroll
    for (int lvl = 0; lvl < 4; lvl++) {
        int Wl = c_hw[lvl];
        const float* vb = g_v + c_voff[lvl] + (size_t)(b * HEADS + head) * Wl * Wl * HD;
        float sc = 0.5f * (float)(Wl - 1);
#pragma unroll
        for (int pt = 0; pt < 4; pt++) {
            int j  = lvl * 4 + pt;
            int ch = ((head * 4 + lvl) * 4 + pt) * 2;
            float ox = tanhf(offp[ch * NQ]) * 0.25f;
            float oy = tanhf(offp[(ch + 1) * NQ]) * 0.25f;
            float aw = attp[j * NQ];
            float x = (refx + ox + 1.f) * sc;
            float y = (refy + oy + 1.f) * sc;
            float x0f = floorf(x), y0f = floorf(y);
            float fx = x - x0f, fy = y - y0f;
            int x0 = (int)x0f, y0 = (int)y0f;
            float s = 0.f;
#pragma unroll
            for (int cy = 0; cy < 2; cy++) {
                int yi = y0 + cy;
                if (yi < 0 || yi >= Wl) continue;
                float wy = cy ? fy : (1.f - fy);
#pragma unroll
                for (int cx = 0; cx < 2; cx++) {
                    int xi = x0 + cx;
                    if (xi < 0 || xi >= Wl) continue;
                    float wx = cx ? fx : (1.f - fx);
                    s += wy * wx * vb[(yi * Wl + xi) * HD + lane];
                }
            }
            acc += aw * s;
        }
    }
    g_S[((size_t)b * 256 + head * HD + lane) * NQ + px] = acc;
}

// ===========================================================================
// Host launcher
// ===========================================================================
extern "C" void kernel_launch(void* const* d_in, const int* in_sizes, int n_in,
                              void* d_out, int out_size) {
    const float* query  = (const float*)d_in[0];
    const float* feats[4] = {(const float*)d_in[1], (const float*)d_in[2],
                             (const float*)d_in[3], (const float*)d_in[4]};
    const float* q_w    = (const float*)d_in[5];
    const float* v_w    = (const float*)d_in[6];
    const float* out_w  = (const float*)d_in[7];
    const float* off_w  = (const float*)d_in[8];
    const float* off_b  = (const float*)d_in[9];
    const float* attn_w = (const float*)d_in[10];
    const float* attn_b = (const float*)d_in[11];
    const float* bng    = (const float*)d_in[12];
    const float* bnb    = (const float*)d_in[13];
    const float* bnm    = (const float*)d_in[14];
    const float* bnv    = (const float*)d_in[15];

    float *pq, *poff, *plogit, *pv, *pS, *pwp;
    __nv_bfloat16 *pqh, *pql, *pwh, *pwl;
    cudaGetSymbolAddress((void**)&pq, g_q);
    cudaGetSymbolAddress((void**)&poff, g_off);
    cudaGetSymbolAddress((void**)&plogit, g_logit);
    cudaGetSymbolAddress((void**)&pv, g_v);
    cudaGetSymbolAddress((void**)&pS, g_S);
    cudaGetSymbolAddress((void**)&pwp, g_wpack);
    cudaGetSymbolAddress((void**)&pqh, g_qh);
    cudaGetSymbolAddress((void**)&pql, g_ql);
    cudaGetSymbolAddress((void**)&pwh, g_wh);
    cudaGetSymbolAddress((void**)&pwl, g_wl);

    cudaFuncSetAttribute(conv_hmma<256>, cudaFuncAttributeMaxDynamicSharedMemorySize, SM_CONV);
    cudaFuncSetAttribute(conv_hmma<128>, cudaFuncAttributeMaxDynamicSharedMemorySize, SM_CONV);

    // ---- weight packs + BN prep ----
    {
        int tot;
        tot = 256 * 256;     pack_weights<<<(tot + 255) / 256, 256>>>(q_w,   pwp + WP_Q,   256, 1);
        for (int l = 0; l < 4; l++) {
            tot = 256 * 256;
            pack_weights<<<(tot + 255) / 256, 256>>>(v_w + l * 65536, pwp + WP_V + l * 65536, 256, 1);
        }
        tot = 256 * 256;     pack_weights<<<(tot + 255) / 256, 256>>>(out_w, pwp + WP_OUT, 256, 1);
        tot = 256 * 2304;    pack_conv_bf16<<<(tot + 255) / 256, 256>>>(off_w,  pwh,           pwl,           256);
        tot = 128 * 2304;    pack_conv_bf16<<<(tot + 255) / 256, 256>>>(attn_w, pwh + WB_ATTN, pwl + WB_ATTN, 128);
        bn_prep<<<1, 256>>>(bng, bnb, bnm, bnv);
    }

    // ---- 1. q projection (fp32) + bf16 split ----
    gemm_conv<1, 0><<<dim3(16, 4, 4), 256>>>(query, pwp + WP_Q, nullptr, pq, 256, 64, 64, nullptr);
    q_split<<<dim3(128, 4), 256>>>();

    // ---- 2/3. offset + logit convs via HMMA ----
    conv_hmma<256><<<dim3(32, 2, 4), 256, SM_CONV>>>(pqh, pql, pwh, pwl, off_b, poff);
    conv_hmma<128><<<dim3(32, 1, 4), 256, SM_CONV>>>(pqh, pql, pwh + WB_ATTN, pwl + WB_ATTN, attn_b, plogit);

    // ---- 4. softmax ----
    softmax16<<<(BATCH * HEADS * NQ + 255) / 256, 256>>>();

    // ---- 5. value projections per level ----
    {
        const int hw[4]   = {64, 32, 16, 8};
        const int voff[4] = {0, 4194304, 5242880, 5505024};
        for (int l = 0; l < 4; l++) {
            int n = hw[l] * hw[l];
            dim3 grid((n + 255) / 256, 4, 4);
            gemm_conv<1, 1><<<grid, 256>>>(feats[l], pwp + WP_V + l * 65536, nullptr,
                                           pv + voff[l], 256, hw[l], hw[l], nullptr);
        }
    }

    // ---- 6. deformable sampling ----
    sample_kernel<<<(BATCH * HEADS * NQ * 32) / 256, 256>>>();

    // ---- 7. output projection + residual + BN + SiLU ----
    gemm_conv<1, 2><<<dim3(16, 4, 4), 256>>>(pS, pwp + WP_OUT, nullptr, (float*)d_out,
                                             256, 64, 64, query);
}